// round 11
// baseline (speedup 1.0000x reference)
#include <cuda_runtime.h>
#include <cstdint>

// AttnSageGCN: B=32768 nodes, K=32 neighbors, D=128, HIDDEN=128 (4x32), H2=256
#define B_NODES 32768
#define SCALE_ATTN 0.17677669529663687f

typedef unsigned long long ull;

// Scratch (device globals; no runtime allocation allowed)
// g_m layout: per node 528 floats, element (h,j) at h*132 + j  (conflict-free banks)
__device__ float g_q[(size_t)B_NODES * 128];
__device__ float g_self[(size_t)B_NODES * 128];
__device__ float g_z[(size_t)B_NODES * 512];    // per node, [h][d] (SCALE folded in)
__device__ float g_m[(size_t)B_NODES * 528];    // per node, [h*132 + j]
__device__ float g_v[(size_t)B_NODES * 128];    // attention output before wo

// ---------------- packed f32x2 helpers (FFMA2) ----------------
__device__ __forceinline__ ull pack2(float lo, float hi) {
    ull r; asm("mov.b64 %0, {%1, %2};" : "=l"(r) : "f"(lo), "f"(hi)); return r;
}
__device__ __forceinline__ float2 unpack2(ull v) {
    float2 f; asm("mov.b64 {%0, %1}, %2;" : "=f"(f.x), "=f"(f.y) : "l"(v)); return f;
}
__device__ __forceinline__ void fma2(ull& d, ull a, ull b) {
    asm("fma.rn.f32x2 %0, %1, %2, %0;" : "+l"(d) : "l"(a), "l"(b));
}

// ---------------- cp.async helpers (base-target, sm_80+) ----------------
__device__ __forceinline__ uint32_t smem_u32(const void* p) {
    uint32_t a;
    asm("{ .reg .u64 t; cvta.to.shared.u64 t, %1; cvt.u32.u64 %0, t; }" : "=r"(a) : "l"(p));
    return a;
}
__device__ __forceinline__ void cp16(uint32_t dst, const void* src) {
    asm volatile("cp.async.cg.shared.global [%0], [%1], 16;" :: "r"(dst), "l"(src) : "memory");
}
#define CP_COMMIT() asm volatile("cp.async.commit_group;" ::: "memory")
#define CP_WAIT0()  asm volatile("cp.async.wait_group 0;" ::: "memory")
#define CP_WAIT1()  asm volatile("cp.async.wait_group 1;" ::: "memory")

// =====================================================================
// Kernel 1 (persistent): q = src @ wq + bq ; self = src @ w_self
// =====================================================================
__global__ void __launch_bounds__(256, 1) k1_proj(
    const float* __restrict__ src, const float* __restrict__ wq,
    const float* __restrict__ bq, const float* __restrict__ wself)
{
    extern __shared__ float sm1[];
    float* W  = sm1;           // [128][256]
    float* bb = sm1 + 32768;   // [256]
    float* xs = sm1 + 33024;   // [32][128]
    int t = threadIdx.x;

    for (int i = t; i < 16384; i += 256) {
        int d = i >> 7, j = i & 127;
        W[d * 256 + j]       = wq[i];
        W[d * 256 + 128 + j] = wself[i];
    }
    if (t < 128) { bb[t] = bq[t]; bb[128 + t] = 0.f; }
    int c = blockIdx.x;
    {
        size_t r0 = (size_t)c * 4096;
        for (int i = t * 4; i < 4096; i += 1024)
            *(float4*)&xs[i] = *(const float4*)&src[r0 + i];
    }
    __syncthreads();

    int tj = t & 63, tk = t >> 6;
    int jb = tj * 4, rb = tk * 8;
    while (c < 1024) {
        int cn = c + gridDim.x;
        float4 pfr[4];
        if (cn < 1024) {
            const float4* s4 = (const float4*)&src[(size_t)cn * 4096 + t * 16];
#pragma unroll
            for (int i = 0; i < 4; i++) pfr[i] = s4[i];
        }
        float4 bj = *(float4*)&bb[jb];
        ull acc[8][2];
#pragma unroll
        for (int i = 0; i < 8; i++) {
            acc[i][0] = pack2(bj.x, bj.y);
            acc[i][1] = pack2(bj.z, bj.w);
        }
#pragma unroll 4
        for (int d = 0; d < 128; d += 2) {
            ulonglong2 w0 = *(ulonglong2*)&W[d * 256 + jb];
            ulonglong2 w1 = *(ulonglong2*)&W[(d + 1) * 256 + jb];
#pragma unroll
            for (int i = 0; i < 8; i++) {
                float2 av = *(float2*)&xs[(rb + i) * 128 + d];
                ull a0 = pack2(av.x, av.x), a1 = pack2(av.y, av.y);
                fma2(acc[i][0], a0, w0.x); fma2(acc[i][1], a0, w0.y);
                fma2(acc[i][0], a1, w1.x); fma2(acc[i][1], a1, w1.y);
            }
        }
        size_t row0 = (size_t)c * 32;
#pragma unroll
        for (int i = 0; i < 8; i++) {
            size_t r = row0 + rb + i;
            float2 u = unpack2(acc[i][0]), v = unpack2(acc[i][1]);
            float4 o = make_float4(u.x, u.y, v.x, v.y);
            if (jb < 128) *(float4*)&g_q[r * 128 + jb] = o;
            else          *(float4*)&g_self[r * 128 + (jb - 128)] = o;
        }
        __syncthreads();
        if (cn < 1024) {
#pragma unroll
            for (int i = 0; i < 4; i++) *(float4*)&xs[t * 16 + i * 4] = pfr[i];
        }
        __syncthreads();
        c = cn;
    }
}

// =====================================================================
// Kernel Z (persistent, cp.async double-buffered):
//   z[b][h][d] = SCALE * sum_j q[b][32h+j] * Wk[d][32h+j]
// =====================================================================
#define ZT_STR 132
#define KZ_QTILE (32 * ZT_STR)           // 4224 floats per q buffer
__global__ void __launch_bounds__(256, 2) kz_proj(const float* __restrict__ wkv)
{
    extern __shared__ float sz[];
    float* WT = sz;                      // [128 cols][132]: WT[c][d] = wkv[d][c]
    float* qs = sz + 128 * ZT_STR;       // 2 x [32][132]
    uint32_t qs_a = smem_u32(qs);
    int t = threadIdx.x;

    {   // load + transpose Wk (coalesced global reads)
        int d = t >> 1, c0 = (t & 1) * 64;
#pragma unroll
        for (int i = 0; i < 16; i++) {
            float4 v = *(const float4*)&wkv[d * 256 + c0 + i * 4];
            WT[(c0 + i * 4 + 0) * ZT_STR + d] = v.x;
            WT[(c0 + i * 4 + 1) * ZT_STR + d] = v.y;
            WT[(c0 + i * 4 + 2) * ZT_STR + d] = v.z;
            WT[(c0 + i * 4 + 3) * ZT_STR + d] = v.w;
        }
    }

    int row = t >> 3, seg = t & 7;       // q tile loader mapping
    int c = blockIdx.x;
    if (c < 1024) {
        const float* src = g_q + ((size_t)c * 32 + row) * 128 + seg * 16;
        uint32_t dst = qs_a + row * 528 + seg * 64;
#pragma unroll
        for (int i = 0; i < 4; i++) cp16(dst + i * 16, src + i * 4);
        CP_COMMIT();
    }
    __syncthreads();   // WT ready

    int hd0 = (t & 63) * 8;
    int h = hd0 >> 7, d0 = hd0 & 127;
    int g0 = (t >> 6) * 8;
    int buf = 0;

    while (c < 1024) {
        int cn = c + gridDim.x;
        if (cn < 1024) {
            const float* src = g_q + ((size_t)cn * 32 + row) * 128 + seg * 16;
            uint32_t dst = qs_a + (buf ^ 1) * (KZ_QTILE * 4) + row * 528 + seg * 64;
#pragma unroll
            for (int i = 0; i < 4; i++) cp16(dst + i * 16, src + i * 4);
            CP_COMMIT();
            CP_WAIT1();          // current buf's group complete
        } else {
            CP_WAIT0();
        }
        __syncthreads();

        const float* qsb = qs + buf * KZ_QTILE;
        size_t n0 = (size_t)c * 32;
        ull acc[8][4];
#pragma unroll
        for (int gg = 0; gg < 8; gg++)
#pragma unroll
            for (int i = 0; i < 4; i++) acc[gg][i] = 0ULL;

#pragma unroll 4
        for (int j = 0; j < 32; j++) {
            const float* wr = &WT[(32 * h + j) * ZT_STR + d0];
            ulonglong2 w0 = *(const ulonglong2*)wr;
            ulonglong2 w1 = *(const ulonglong2*)(wr + 4);
#pragma unroll
            for (int gg = 0; gg < 8; gg++) {
                float qv = qsb[(g0 + gg) * ZT_STR + 32 * h + j];
                ull qp = pack2(qv, qv);
                fma2(acc[gg][0], qp, w0.x); fma2(acc[gg][1], qp, w0.y);
                fma2(acc[gg][2], qp, w1.x); fma2(acc[gg][3], qp, w1.y);
            }
        }
#pragma unroll
        for (int gg = 0; gg < 8; gg++) {
            float2 a = unpack2(acc[gg][0]), b = unpack2(acc[gg][1]);
            float2 cc = unpack2(acc[gg][2]), dd = unpack2(acc[gg][3]);
            float4 o0 = make_float4(a.x * SCALE_ATTN, a.y * SCALE_ATTN,
                                    b.x * SCALE_ATTN, b.y * SCALE_ATTN);
            float4 o1 = make_float4(cc.x * SCALE_ATTN, cc.y * SCALE_ATTN,
                                    dd.x * SCALE_ATTN, dd.y * SCALE_ATTN);
            size_t base = (n0 + g0 + gg) * 512 + hd0;
            *(float4*)&g_z[base]     = o0;
            *(float4*)&g_z[base + 4] = o1;
        }
        __syncthreads();   // everyone done reading buf before it is refilled
        buf ^= 1; c = cn;
    }
}

// =====================================================================
// Kernel 2: streaming attention, warp-per-node, FULLY double-buffered.
//   logits[h][k] = n_k . z_h ; softmax over k (shfl); m_h = sum_k p n_k
//   m written in padded layout g_m[node*528 + h*132 + d]
// =====================================================================
#define NB_STR 132                       // floats per n row (pad)
#define NB_WARP (NB_STR * 32)            // 4224 floats per n buffer
#define K2_NW 4                          // warps per CTA
#define OFF_ZB (K2_NW * 2 * NB_WARP)     // 33792
#define OFF_PB (OFF_ZB + K2_NW * 2 * 512) // 37888
#define K2_SMEMF (OFF_PB + K2_NW * 128)  // 38400 floats = 153600 B

__device__ __forceinline__ void k2_issue_node(uint32_t sb, int w, int buf,
                                              const float* __restrict__ nbr,
                                              int nd, int lane) {
    const float* nsrc = nbr + (size_t)nd * 4096;
    uint32_t nb_a = sb + ((w * 2 + buf) * NB_WARP) * 4;
#pragma unroll
    for (int i = 0; i < 32; i++)
        cp16(nb_a + i * 528 + lane * 16, nsrc + i * 128 + lane * 4);
    const float* zsrc = g_z + (size_t)nd * 512 + lane * 16;
    uint32_t zb_a = sb + (OFF_ZB + (w * 2 + buf) * 512) * 4;
#pragma unroll
    for (int i = 0; i < 4; i++) cp16(zb_a + lane * 64 + i * 16, zsrc + i * 4);
    CP_COMMIT();
}

__global__ void __launch_bounds__(128, 1) k2_attn(const float* __restrict__ nbr)
{
    extern __shared__ float s2[];
    uint32_t sb = smem_u32(s2);
    int t = threadIdx.x, w = t >> 5, lane = t & 31;
    float* pb = s2 + OFF_PB + w * 128;

    int node = blockIdx.x * K2_NW + w;
    const int stride = gridDim.x * K2_NW;

    if (node < B_NODES) k2_issue_node(sb, w, 0, nbr, node, lane);
    if (node + stride < B_NODES) k2_issue_node(sb, w, 1, nbr, node + stride, lane);

    int buf = 0;
    while (node < B_NODES) {
        int nxt = node + stride;
        if (nxt < B_NODES) CP_WAIT1(); else CP_WAIT0();
        __syncwarp();

        const float* nb = s2 + (w * 2 + buf) * NB_WARP;
        const float* zb = s2 + OFF_ZB + (w * 2 + buf) * 512;

        // ---- logits: lane = neighbor k ----
        const float* row = nb + lane * NB_STR;
        ull lga[4], lgb[4];
#pragma unroll
        for (int h = 0; h < 4; h++) { lga[h] = 0ULL; lgb[h] = 0ULL; }
#pragma unroll 4
        for (int d4 = 0; d4 < 32; d4++) {
            ulonglong2 nv = *(const ulonglong2*)(row + d4 * 4);
#pragma unroll
            for (int h = 0; h < 4; h++) {
                ulonglong2 zv = *(const ulonglong2*)(zb + h * 128 + d4 * 4);
                fma2(lga[h], nv.x, zv.x);
                fma2(lgb[h], nv.y, zv.y);
            }
        }
        float p[4];
#pragma unroll
        for (int h = 0; h < 4; h++) {
            float2 a = unpack2(lga[h]), b = unpack2(lgb[h]);
            float lg = (a.x + a.y) + (b.x + b.y);
            float mx = lg;
#pragma unroll
            for (int o = 16; o > 0; o >>= 1)
                mx = fmaxf(mx, __shfl_xor_sync(0xffffffffu, mx, o));
            float e = __expf(lg - mx);
            float sum = e;
#pragma unroll
            for (int o = 16; o > 0; o >>= 1)
                sum += __shfl_xor_sync(0xffffffffu, sum, o);
            p[h] = e / sum;
        }
        *(float4*)&pb[lane * 4] = make_float4(p[0], p[1], p[2], p[3]);
        __syncwarp();

        // ---- m: lane owns d-chunk [4*lane, 4*lane+4) ----
        float4 mac[4];
#pragma unroll
        for (int h = 0; h < 4; h++) mac[h] = make_float4(0.f, 0.f, 0.f, 0.f);
#pragma unroll 4
        for (int k = 0; k < 32; k++) {
            float4 p4 = *(const float4*)&pb[k * 4];
            float4 nv = *(const float4*)&nb[k * NB_STR + 4 * lane];
            const float* pp = &p4.x;
#pragma unroll
            for (int h = 0; h < 4; h++) {
                mac[h].x = fmaf(pp[h], nv.x, mac[h].x);
                mac[h].y = fmaf(pp[h], nv.y, mac[h].y);
                mac[h].z = fmaf(pp[h], nv.z, mac[h].z);
                mac[h].w = fmaf(pp[h], nv.w, mac[h].w);
            }
        }

        size_t mb = (size_t)node * 528;
#pragma unroll
        for (int h = 0; h < 4; h++)
            *(float4*)&g_m[mb + h * 132 + 4 * lane] = mac[h];

        __syncwarp();      // all lanes done reading buf
        int nn2 = node + 2 * stride;
        if (nn2 < B_NODES) k2_issue_node(sb, w, buf, nbr, nn2, lane);

        node = nxt; buf ^= 1;
    }
}

// =====================================================================
// Kernel 3a (persistent, double-buffered, LDS-minimized):
//   v[b][32h+c] = bv[32h+c] + sum_j m[b][h][j] * Wv[j][32h+c]
//   128 threads; thread tile = 8 nodes x 4 cols; m reads conflict-free
// =====================================================================
#define MV_STR 528
#define MV_TILE (32 * MV_STR)            // 16896 floats per m buffer
__global__ void __launch_bounds__(128, 1) k3a_v(
    const float* __restrict__ wkv, const float* __restrict__ bkv)
{
    extern __shared__ float sa[];
    float* Wv  = sa;                                  // [128][132]
    float* ms  = sa + 128 * ZT_STR;                   // 2 x [32 nodes][528]
    float* bvs = sa + 128 * ZT_STR + 2 * MV_TILE;     // [128]
    uint32_t ms_a = smem_u32(ms);
    int t = threadIdx.x;

    {   // Wv: row t of 128 floats
#pragma unroll 8
        for (int i = 0; i < 32; i++)
            *(float4*)&Wv[t * ZT_STR + i * 4] =
                *(const float4*)&wkv[t * 256 + 128 + i * 4];
    }
    if (t < 32) *(float4*)&bvs[t * 4] = *(const float4*)&bkv[128 + t * 4];

    int c = blockIdx.x;
    if (c < 1024) {   // linear copy: g_m tile stride matches SMEM stride (528)
        const float* src = g_m + (size_t)c * MV_TILE;
        for (int i = t; i < 4224; i += 128) cp16(ms_a + i * 16, src + i * 4);
        CP_COMMIT();
    }
    __syncthreads();   // Wv/bvs ready

    int c0 = (t & 31) * 4, h = c0 >> 5, g0 = (t >> 5) * 8;
    float4 bv4 = *(float4*)&bvs[c0];
    int buf = 0;

    while (c < 1024) {
        int cn = c + gridDim.x;
        if (cn < 1024) {
            const float* src = g_m + (size_t)cn * MV_TILE;
            uint32_t dst = ms_a + (buf ^ 1) * (MV_TILE * 4);
            for (int i = t; i < 4224; i += 128) cp16(dst + i * 16, src + i * 4);
            CP_COMMIT();
            CP_WAIT1();
        } else {
            CP_WAIT0();
        }
        __syncthreads();

        const float* msb = ms + buf * MV_TILE;
        size_t n0 = (size_t)c * 32;
        ull acc[8][2];
#pragma unroll
        for (int gg = 0; gg < 8; gg++) {
            acc[gg][0] = pack2(bv4.x, bv4.y);
            acc[gg][1] = pack2(bv4.z, bv4.w);
        }
#pragma unroll 4
        for (int j = 0; j < 128; j++) {
            ulonglong2 w2 = *(const ulonglong2*)&Wv[j * ZT_STR + c0];
#pragma unroll
            for (int gg = 0; gg < 8; gg++) {
                float mv = msb[(g0 + gg) * MV_STR + h * 132 + j];
                ull mp = pack2(mv, mv);
                fma2(acc[gg][0], mp, w2.x);
                fma2(acc[gg][1], mp, w2.y);
            }
        }
#pragma unroll
        for (int gg = 0; gg < 8; gg++) {
            float2 u = unpack2(acc[gg][0]), v = unpack2(acc[gg][1]);
            *(float4*)&g_v[(n0 + g0 + gg) * 128 + c0] = make_float4(u.x, u.y, v.x, v.y);
        }
        __syncthreads();   // all reads of buf done before refill
        buf ^= 1; c = cn;
    }
}

// =====================================================================
// Kernel 3b (persistent): out = relu(g_self + g_v @ wo + bo)
// =====================================================================
__global__ void __launch_bounds__(256, 1) k3_out(
    const float* __restrict__ wo, const float* __restrict__ bo,
    float* __restrict__ out)
{
    extern __shared__ float sm3[];
    float* W  = sm3;            // [128][128]
    float* bb = sm3 + 16384;    // [128]
    float* os = sm3 + 16512;    // [64][128]
    int t = threadIdx.x;

    for (int i = t * 4; i < 16384; i += 1024)
        *(float4*)&W[i] = *(const float4*)&wo[i];
    if (t < 32) *(float4*)&bb[t * 4] = *(const float4*)&bo[t * 4];
    int c = blockIdx.x;
    {
        size_t r0 = (size_t)c * 8192;
        for (int i = t * 4; i < 8192; i += 1024)
            *(float4*)&os[i] = *(const float4*)&g_v[r0 + i];
    }
    __syncthreads();

    int tj = t & 31, tk = t >> 5;
    int jb = tj * 4, rb = tk * 8;
    while (c < 512) {
        int cn = c + gridDim.x;
        float4 pfr[8];
        if (cn < 512) {
            const float4* s4 = (const float4*)&g_v[(size_t)cn * 8192 + t * 32];
#pragma unroll
            for (int i = 0; i < 8; i++) pfr[i] = s4[i];
        }
        float4 bj = *(float4*)&bb[jb];
        ull acc[8][2];
#pragma unroll
        for (int i = 0; i < 8; i++) {
            acc[i][0] = pack2(bj.x, bj.y);
            acc[i][1] = pack2(bj.z, bj.w);
        }
#pragma unroll 4
        for (int d = 0; d < 128; d += 2) {
            ulonglong2 w0 = *(ulonglong2*)&W[d * 128 + jb];
            ulonglong2 w1 = *(ulonglong2*)&W[(d + 1) * 128 + jb];
#pragma unroll
            for (int i = 0; i < 8; i++) {
                float2 av = *(float2*)&os[(rb + i) * 128 + d];
                ull a0 = pack2(av.x, av.x), a1 = pack2(av.y, av.y);
                fma2(acc[i][0], a0, w0.x); fma2(acc[i][1], a0, w0.y);
                fma2(acc[i][0], a1, w1.x); fma2(acc[i][1], a1, w1.y);
            }
        }
        size_t row0 = (size_t)c * 64;
#pragma unroll
        for (int i = 0; i < 8; i++) {
            size_t r = row0 + rb + i;
            float4 s4 = *(const float4*)&g_self[r * 128 + jb];
            float2 u = unpack2(acc[i][0]), v = unpack2(acc[i][1]);
            float4 o = make_float4(fmaxf(u.x + s4.x, 0.f), fmaxf(u.y + s4.y, 0.f),
                                   fmaxf(v.x + s4.z, 0.f), fmaxf(v.y + s4.w, 0.f));
            *(float4*)&out[r * 128 + jb] = o;
        }
        __syncthreads();
        if (cn < 512) {
#pragma unroll
            for (int i = 0; i < 8; i++) *(float4*)&os[t * 32 + i * 4] = pfr[i];
        }
        __syncthreads();
        c = cn;
    }
}

// =====================================================================
// Launch
// =====================================================================
#define K1_SMEM 148480
#define KZ_SMEM ((128 * ZT_STR + 2 * KZ_QTILE) * 4)                    // 101376
#define K2_SMEM (K2_SMEMF * 4)                                         // 153600
#define K3A_SMEM ((128 * ZT_STR + 2 * MV_TILE + 128) * 4)              // 203264
#define K3_SMEM 98816

extern "C" void kernel_launch(void* const* d_in, const int* in_sizes, int n_in,
                              void* d_out, int out_size)
{
    const float* src   = (const float*)d_in[0];
    const float* nbr   = (const float*)d_in[1];
    const float* wq    = (const float*)d_in[2];
    const float* bq    = (const float*)d_in[3];
    const float* wkv   = (const float*)d_in[4];
    const float* bkv   = (const float*)d_in[5];
    const float* wo    = (const float*)d_in[6];
    const float* bo    = (const float*)d_in[7];
    const float* wself = (const float*)d_in[8];
    float* out = (float*)d_out;

    cudaFuncSetAttribute(k1_proj, cudaFuncAttributeMaxDynamicSharedMemorySize, K1_SMEM);
    cudaFuncSetAttribute(kz_proj, cudaFuncAttributeMaxDynamicSharedMemorySize, KZ_SMEM);
    cudaFuncSetAttribute(k2_attn, cudaFuncAttributeMaxDynamicSharedMemorySize, K2_SMEM);
    cudaFuncSetAttribute(k3a_v,   cudaFuncAttributeMaxDynamicSharedMemorySize, K3A_SMEM);
    cudaFuncSetAttribute(k3_out,  cudaFuncAttributeMaxDynamicSharedMemorySize, K3_SMEM);

    int dev = 0;
    cudaGetDevice(&dev);
    int nsm = 148;
    cudaDeviceGetAttribute(&nsm, cudaDevAttrMultiProcessorCount, dev);

    k1_proj<<<nsm, 256, K1_SMEM>>>(src, wq, bq, wself);
    kz_proj<<<2 * nsm, 256, KZ_SMEM>>>(wkv);
    k2_attn<<<nsm, 128, K2_SMEM>>>(nbr);
    k3a_v<<<nsm, 128, K3A_SMEM>>>(wkv, bkv);
    k3_out<<<nsm, 256, K3_SMEM>>>(wo, bo, out);
}

// round 12
// speedup vs baseline: 1.0672x; 1.0672x over previous
#include <cuda_runtime.h>
#include <cstdint>

// AttnSageGCN: B=32768 nodes, K=32 neighbors, D=128, HIDDEN=128 (4x32), H2=256
#define B_NODES 32768
#define SCALE_ATTN 0.17677669529663687f

typedef unsigned long long ull;

// Scratch (device globals; no runtime allocation allowed)
// g_m layout: per node 528 floats, element (h,j) at h*132 + j (conflict-free banks)
__device__ float g_q[(size_t)B_NODES * 128];
__device__ float g_self[(size_t)B_NODES * 128];
__device__ float g_z[(size_t)B_NODES * 512];    // per node, [h][d] (SCALE folded in)
__device__ float g_m[(size_t)B_NODES * 528];    // per node, [h*132 + j]
__device__ float g_v[(size_t)B_NODES * 128];    // attention output before wo

// ---------------- packed f32x2 helpers (FFMA2) ----------------
__device__ __forceinline__ ull pack2(float lo, float hi) {
    ull r; asm("mov.b64 %0, {%1, %2};" : "=l"(r) : "f"(lo), "f"(hi)); return r;
}
__device__ __forceinline__ float2 unpack2(ull v) {
    float2 f; asm("mov.b64 {%0, %1}, %2;" : "=f"(f.x), "=f"(f.y) : "l"(v)); return f;
}
__device__ __forceinline__ void fma2(ull& d, ull a, ull b) {
    asm("fma.rn.f32x2 %0, %1, %2, %0;" : "+l"(d) : "l"(a), "l"(b));
}

// ---------------- cp.async helpers (base-target, sm_80+) ----------------
__device__ __forceinline__ uint32_t smem_u32(const void* p) {
    uint32_t a;
    asm("{ .reg .u64 t; cvta.to.shared.u64 t, %1; cvt.u32.u64 %0, t; }" : "=r"(a) : "l"(p));
    return a;
}
__device__ __forceinline__ void cp16(uint32_t dst, const void* src) {
    asm volatile("cp.async.cg.shared.global [%0], [%1], 16;" :: "r"(dst), "l"(src) : "memory");
}
#define CP_COMMIT() asm volatile("cp.async.commit_group;" ::: "memory")
#define CP_WAIT0()  asm volatile("cp.async.wait_group 0;" ::: "memory")
#define CP_WAIT1()  asm volatile("cp.async.wait_group 1;" ::: "memory")

// =====================================================================
// Kernel 1 (persistent): q = src @ wq + bq ; self = src @ w_self
// =====================================================================
__global__ void __launch_bounds__(256, 1) k1_proj(
    const float* __restrict__ src, const float* __restrict__ wq,
    const float* __restrict__ bq, const float* __restrict__ wself)
{
    extern __shared__ float sm1[];
    float* W  = sm1;           // [128][256]
    float* bb = sm1 + 32768;   // [256]
    float* xs = sm1 + 33024;   // [32][128]
    int t = threadIdx.x;

    for (int i = t; i < 16384; i += 256) {
        int d = i >> 7, j = i & 127;
        W[d * 256 + j]       = wq[i];
        W[d * 256 + 128 + j] = wself[i];
    }
    if (t < 128) { bb[t] = bq[t]; bb[128 + t] = 0.f; }
    int c = blockIdx.x;
    {
        size_t r0 = (size_t)c * 4096;
        for (int i = t * 4; i < 4096; i += 1024)
            *(float4*)&xs[i] = *(const float4*)&src[r0 + i];
    }
    __syncthreads();

    int tj = t & 63, tk = t >> 6;
    int jb = tj * 4, rb = tk * 8;
    while (c < 1024) {
        int cn = c + gridDim.x;
        float4 pfr[4];
        if (cn < 1024) {
            const float4* s4 = (const float4*)&src[(size_t)cn * 4096 + t * 16];
#pragma unroll
            for (int i = 0; i < 4; i++) pfr[i] = s4[i];
        }
        float4 bj = *(float4*)&bb[jb];
        ull acc[8][2];
#pragma unroll
        for (int i = 0; i < 8; i++) {
            acc[i][0] = pack2(bj.x, bj.y);
            acc[i][1] = pack2(bj.z, bj.w);
        }
#pragma unroll 4
        for (int d = 0; d < 128; d += 2) {
            ulonglong2 w0 = *(ulonglong2*)&W[d * 256 + jb];
            ulonglong2 w1 = *(ulonglong2*)&W[(d + 1) * 256 + jb];
#pragma unroll
            for (int i = 0; i < 8; i++) {
                float2 av = *(float2*)&xs[(rb + i) * 128 + d];
                ull a0 = pack2(av.x, av.x), a1 = pack2(av.y, av.y);
                fma2(acc[i][0], a0, w0.x); fma2(acc[i][1], a0, w0.y);
                fma2(acc[i][0], a1, w1.x); fma2(acc[i][1], a1, w1.y);
            }
        }
        size_t row0 = (size_t)c * 32;
#pragma unroll
        for (int i = 0; i < 8; i++) {
            size_t r = row0 + rb + i;
            float2 u = unpack2(acc[i][0]), v = unpack2(acc[i][1]);
            float4 o = make_float4(u.x, u.y, v.x, v.y);
            if (jb < 128) *(float4*)&g_q[r * 128 + jb] = o;
            else          *(float4*)&g_self[r * 128 + (jb - 128)] = o;
        }
        __syncthreads();
        if (cn < 1024) {
#pragma unroll
            for (int i = 0; i < 4; i++) *(float4*)&xs[t * 16 + i * 4] = pfr[i];
        }
        __syncthreads();
        c = cn;
    }
}

// =====================================================================
// Kernel Z (persistent, cp.async double-buffered):
//   z[b][h][d] = SCALE * sum_j q[b][32h+j] * Wk[d][32h+j]
// =====================================================================
#define ZT_STR 132
#define KZ_QTILE (32 * ZT_STR)           // 4224 floats per q buffer
__global__ void __launch_bounds__(256, 2) kz_proj(const float* __restrict__ wkv)
{
    extern __shared__ float sz[];
    float* WT = sz;                      // [128 cols][132]: WT[c][d] = wkv[d][c]
    float* qs = sz + 128 * ZT_STR;       // 2 x [32][132]
    uint32_t qs_a = smem_u32(qs);
    int t = threadIdx.x;

    {   // load + transpose Wk (coalesced global reads)
        int d = t >> 1, c0 = (t & 1) * 64;
#pragma unroll
        for (int i = 0; i < 16; i++) {
            float4 v = *(const float4*)&wkv[d * 256 + c0 + i * 4];
            WT[(c0 + i * 4 + 0) * ZT_STR + d] = v.x;
            WT[(c0 + i * 4 + 1) * ZT_STR + d] = v.y;
            WT[(c0 + i * 4 + 2) * ZT_STR + d] = v.z;
            WT[(c0 + i * 4 + 3) * ZT_STR + d] = v.w;
        }
    }

    int row = t >> 3, seg = t & 7;       // q tile loader mapping
    int c = blockIdx.x;
    if (c < 1024) {
        const float* src = g_q + ((size_t)c * 32 + row) * 128 + seg * 16;
        uint32_t dst = qs_a + row * 528 + seg * 64;
#pragma unroll
        for (int i = 0; i < 4; i++) cp16(dst + i * 16, src + i * 4);
        CP_COMMIT();
    }
    __syncthreads();   // WT ready

    int hd0 = (t & 63) * 8;
    int h = hd0 >> 7, d0 = hd0 & 127;
    int g0 = (t >> 6) * 8;
    int buf = 0;

    while (c < 1024) {
        int cn = c + gridDim.x;
        if (cn < 1024) {
            const float* src = g_q + ((size_t)cn * 32 + row) * 128 + seg * 16;
            uint32_t dst = qs_a + (buf ^ 1) * (KZ_QTILE * 4) + row * 528 + seg * 64;
#pragma unroll
            for (int i = 0; i < 4; i++) cp16(dst + i * 16, src + i * 4);
            CP_COMMIT();
            CP_WAIT1();          // current buf's group complete
        } else {
            CP_WAIT0();
        }
        __syncthreads();

        const float* qsb = qs + buf * KZ_QTILE;
        size_t n0 = (size_t)c * 32;
        ull acc[8][4];
#pragma unroll
        for (int gg = 0; gg < 8; gg++)
#pragma unroll
            for (int i = 0; i < 4; i++) acc[gg][i] = 0ULL;

#pragma unroll 4
        for (int j = 0; j < 32; j++) {
            const float* wr = &WT[(32 * h + j) * ZT_STR + d0];
            ulonglong2 w0 = *(const ulonglong2*)wr;
            ulonglong2 w1 = *(const ulonglong2*)(wr + 4);
#pragma unroll
            for (int gg = 0; gg < 8; gg++) {
                float qv = qsb[(g0 + gg) * ZT_STR + 32 * h + j];
                ull qp = pack2(qv, qv);
                fma2(acc[gg][0], qp, w0.x); fma2(acc[gg][1], qp, w0.y);
                fma2(acc[gg][2], qp, w1.x); fma2(acc[gg][3], qp, w1.y);
            }
        }
#pragma unroll
        for (int gg = 0; gg < 8; gg++) {
            float2 a = unpack2(acc[gg][0]), b = unpack2(acc[gg][1]);
            float2 cc = unpack2(acc[gg][2]), dd = unpack2(acc[gg][3]);
            float4 o0 = make_float4(a.x * SCALE_ATTN, a.y * SCALE_ATTN,
                                    b.x * SCALE_ATTN, b.y * SCALE_ATTN);
            float4 o1 = make_float4(cc.x * SCALE_ATTN, cc.y * SCALE_ATTN,
                                    dd.x * SCALE_ATTN, dd.y * SCALE_ATTN);
            size_t base = (n0 + g0 + gg) * 512 + hd0;
            *(float4*)&g_z[base]     = o0;
            *(float4*)&g_z[base + 4] = o1;
        }
        __syncthreads();   // everyone done reading buf before it is refilled
        buf ^= 1; c = cn;
    }
}

// =====================================================================
// Kernel 2: streaming attention. Warp-per-node, 8 warps (proven), with
// half-overlap refill. p stored pre-duplicated -> m-loop runs on FFMA2.
// m written in padded layout g_m[node*528 + h*132 + d]
// =====================================================================
#define NB_STR 132                    // floats per n row (pad)
#define NB_WARP (NB_STR * 32)         // 4224 floats per warp buffer
#define OFF_ZB  (NB_WARP * 8)         // 33792
#define OFF_PB  (OFF_ZB + 8 * 512)    // 37888
#define K2_SMEMF (OFF_PB + 8 * 256)   // 39936 floats = 159744 B

__device__ __forceinline__ void k2_issue_rows(uint32_t nb_a, const float* nsrc,
                                              int lane, int i0, int i1) {
#pragma unroll
    for (int i = i0; i < i1; i++)
        cp16(nb_a + i * 528 + lane * 16, nsrc + i * 128 + lane * 4);
}

__global__ void __launch_bounds__(256, 1) k2_attn(const float* __restrict__ nbr)
{
    extern __shared__ float s2[];
    uint32_t sb = smem_u32(s2);
    int t = threadIdx.x, w = t >> 5, lane = t & 31;
    float* nb = s2 + w * NB_WARP;
    float* zb = s2 + OFF_ZB + w * 512;
    float* pb = s2 + OFF_PB + w * 256;   // 32 k x 4 h x (p,p) duplicated
    uint32_t nb_a = sb + (w * NB_WARP) * 4;
    uint32_t zb_a = sb + (OFF_ZB + w * 512) * 4;

    int node = blockIdx.x * 8 + w;
    const int stride = gridDim.x * 8;

    if (node < B_NODES) {   // prologue: full n tile + z for node0
        const float* nsrc = nbr + (size_t)node * 4096;
        k2_issue_rows(nb_a, nsrc, lane, 0, 32);
        const float* zsrc = g_z + (size_t)node * 512 + lane * 16;
#pragma unroll
        for (int i = 0; i < 4; i++) cp16(zb_a + lane * 64 + i * 16, zsrc + i * 4);
        CP_COMMIT();
    }

    while (node < B_NODES) {
        int nxt = node + stride;
        CP_WAIT0();
        __syncwarp();

        // ---- logits: lane = neighbor k ----
        const float* row = nb + lane * NB_STR;
        ull lga[4], lgb[4];
#pragma unroll
        for (int h = 0; h < 4; h++) { lga[h] = 0ULL; lgb[h] = 0ULL; }
#pragma unroll 4
        for (int d4 = 0; d4 < 32; d4++) {
            ulonglong2 nv = *(const ulonglong2*)(row + d4 * 4);
#pragma unroll
            for (int h = 0; h < 4; h++) {
                ulonglong2 zv = *(const ulonglong2*)(zb + h * 128 + d4 * 4);
                fma2(lga[h], nv.x, zv.x);
                fma2(lgb[h], nv.y, zv.y);
            }
        }
        float p[4];
#pragma unroll
        for (int h = 0; h < 4; h++) {
            float2 a = unpack2(lga[h]), b = unpack2(lgb[h]);
            float lg = (a.x + a.y) + (b.x + b.y);
            float mx = lg;
#pragma unroll
            for (int o = 16; o > 0; o >>= 1)
                mx = fmaxf(mx, __shfl_xor_sync(0xffffffffu, mx, o));
            float e = __expf(lg - mx);
            float sum = e;
#pragma unroll
            for (int o = 16; o > 0; o >>= 1)
                sum += __shfl_xor_sync(0xffffffffu, sum, o);
            p[h] = e / sum;
        }
        // store p DUPLICATED: pb[k*8 + 2h] = pb[k*8 + 2h + 1] = p[h]
        *(float4*)&pb[lane * 8]     = make_float4(p[0], p[0], p[1], p[1]);
        *(float4*)&pb[lane * 8 + 4] = make_float4(p[2], p[2], p[3], p[3]);
        __syncwarp();

        // ---- m (FFMA2): lane owns d-chunk [4*lane, 4*lane+4) ----
        ull mac[4][2];
#pragma unroll
        for (int h = 0; h < 4; h++) { mac[h][0] = 0ULL; mac[h][1] = 0ULL; }
#pragma unroll 4
        for (int k = 0; k < 16; k++) {
            ulonglong2 pa = *(const ulonglong2*)&pb[k * 8];      // (p0,p0),(p1,p1)
            ulonglong2 pc = *(const ulonglong2*)&pb[k * 8 + 4];  // (p2,p2),(p3,p3)
            ulonglong2 nv = *(const ulonglong2*)&nb[k * NB_STR + 4 * lane];
            fma2(mac[0][0], pa.x, nv.x); fma2(mac[0][1], pa.x, nv.y);
            fma2(mac[1][0], pa.y, nv.x); fma2(mac[1][1], pa.y, nv.y);
            fma2(mac[2][0], pc.x, nv.x); fma2(mac[2][1], pc.x, nv.y);
            fma2(mac[3][0], pc.y, nv.x); fma2(mac[3][1], pc.y, nv.y);
        }
        if (nxt < B_NODES) {   // rows 0..15 consumed -> refill early
            __syncwarp();      // all lanes done reading rows 0..15
            k2_issue_rows(nb_a, nbr + (size_t)nxt * 4096, lane, 0, 16);
        }
#pragma unroll 4
        for (int k = 16; k < 32; k++) {
            ulonglong2 pa = *(const ulonglong2*)&pb[k * 8];
            ulonglong2 pc = *(const ulonglong2*)&pb[k * 8 + 4];
            ulonglong2 nv = *(const ulonglong2*)&nb[k * NB_STR + 4 * lane];
            fma2(mac[0][0], pa.x, nv.x); fma2(mac[0][1], pa.x, nv.y);
            fma2(mac[1][0], pa.y, nv.x); fma2(mac[1][1], pa.y, nv.y);
            fma2(mac[2][0], pc.x, nv.x); fma2(mac[2][1], pc.x, nv.y);
            fma2(mac[3][0], pc.y, nv.x); fma2(mac[3][1], pc.y, nv.y);
        }
        if (nxt < B_NODES) {
            __syncwarp();      // all lanes done reading rows 16..31 and zb
            k2_issue_rows(nb_a, nbr + (size_t)nxt * 4096, lane, 16, 32);
            const float* zsrc = g_z + (size_t)nxt * 512 + lane * 16;
#pragma unroll
            for (int i = 0; i < 4; i++) cp16(zb_a + lane * 64 + i * 16, zsrc + i * 4);
            CP_COMMIT();
        }

        size_t mb = (size_t)node * 528;
#pragma unroll
        for (int h = 0; h < 4; h++) {
            float2 u = unpack2(mac[h][0]), v = unpack2(mac[h][1]);
            *(float4*)&g_m[mb + h * 132 + 4 * lane] = make_float4(u.x, u.y, v.x, v.y);
        }

        node = nxt;
    }
}

// =====================================================================
// Kernel 3a (persistent, double-buffered, LDS-minimized):
//   v[b][32h+c] = bv[32h+c] + sum_j m[b][h][j] * Wv[j][32h+c]
//   128 threads; thread tile = 8 nodes x 4 cols; m reads conflict-free
// =====================================================================
#define MV_STR 528
#define MV_TILE (32 * MV_STR)            // 16896 floats per m buffer
__global__ void __launch_bounds__(128, 1) k3a_v(
    const float* __restrict__ wkv, const float* __restrict__ bkv)
{
    extern __shared__ float sa[];
    float* Wv  = sa;                                  // [128][132]
    float* ms  = sa + 128 * ZT_STR;                   // 2 x [32 nodes][528]
    float* bvs = sa + 128 * ZT_STR + 2 * MV_TILE;     // [128]
    uint32_t ms_a = smem_u32(ms);
    int t = threadIdx.x;

    {   // Wv: row t of 128 floats
#pragma unroll 8
        for (int i = 0; i < 32; i++)
            *(float4*)&Wv[t * ZT_STR + i * 4] =
                *(const float4*)&wkv[t * 256 + 128 + i * 4];
    }
    if (t < 32) *(float4*)&bvs[t * 4] = *(const float4*)&bkv[128 + t * 4];

    int c = blockIdx.x;
    if (c < 1024) {   // linear copy: g_m tile stride matches SMEM stride (528)
        const float* src = g_m + (size_t)c * MV_TILE;
        for (int i = t; i < 4224; i += 128) cp16(ms_a + i * 16, src + i * 4);
        CP_COMMIT();
    }
    __syncthreads();   // Wv/bvs ready

    int c0 = (t & 31) * 4, h = c0 >> 5, g0 = (t >> 5) * 8;
    float4 bv4 = *(float4*)&bvs[c0];
    int buf = 0;

    while (c < 1024) {
        int cn = c + gridDim.x;
        if (cn < 1024) {
            const float* src = g_m + (size_t)cn * MV_TILE;
            uint32_t dst = ms_a + (buf ^ 1) * (MV_TILE * 4);
            for (int i = t; i < 4224; i += 128) cp16(dst + i * 16, src + i * 4);
            CP_COMMIT();
            CP_WAIT1();
        } else {
            CP_WAIT0();
        }
        __syncthreads();

        const float* msb = ms + buf * MV_TILE;
        size_t n0 = (size_t)c * 32;
        ull acc[8][2];
#pragma unroll
        for (int gg = 0; gg < 8; gg++) {
            acc[gg][0] = pack2(bv4.x, bv4.y);
            acc[gg][1] = pack2(bv4.z, bv4.w);
        }
#pragma unroll 4
        for (int j = 0; j < 128; j++) {
            ulonglong2 w2 = *(const ulonglong2*)&Wv[j * ZT_STR + c0];
#pragma unroll
            for (int gg = 0; gg < 8; gg++) {
                float mv = msb[(g0 + gg) * MV_STR + h * 132 + j];
                ull mp = pack2(mv, mv);
                fma2(acc[gg][0], mp, w2.x);
                fma2(acc[gg][1], mp, w2.y);
            }
        }
#pragma unroll
        for (int gg = 0; gg < 8; gg++) {
            float2 u = unpack2(acc[gg][0]), v = unpack2(acc[gg][1]);
            *(float4*)&g_v[(n0 + g0 + gg) * 128 + c0] = make_float4(u.x, u.y, v.x, v.y);
        }
        __syncthreads();   // all reads of buf done before refill
        buf ^= 1; c = cn;
    }
}

// =====================================================================
// Kernel 3b (persistent): out = relu(g_self + g_v @ wo + bo)
// =====================================================================
__global__ void __launch_bounds__(256, 1) k3_out(
    const float* __restrict__ wo, const float* __restrict__ bo,
    float* __restrict__ out)
{
    extern __shared__ float sm3[];
    float* W  = sm3;            // [128][128]
    float* bb = sm3 + 16384;    // [128]
    float* os = sm3 + 16512;    // [64][128]
    int t = threadIdx.x;

    for (int i = t * 4; i < 16384; i += 1024)
        *(float4*)&W[i] = *(const float4*)&wo[i];
    if (t < 32) *(float4*)&bb[t * 4] = *(const float4*)&bo[t * 4];
    int c = blockIdx.x;
    {
        size_t r0 = (size_t)c * 8192;
        for (int i = t * 4; i < 8192; i += 1024)
            *(float4*)&os[i] = *(const float4*)&g_v[r0 + i];
    }
    __syncthreads();

    int tj = t & 31, tk = t >> 5;
    int jb = tj * 4, rb = tk * 8;
    while (c < 512) {
        int cn = c + gridDim.x;
        float4 pfr[8];
        if (cn < 512) {
            const float4* s4 = (const float4*)&g_v[(size_t)cn * 8192 + t * 32];
#pragma unroll
            for (int i = 0; i < 8; i++) pfr[i] = s4[i];
        }
        float4 bj = *(float4*)&bb[jb];
        ull acc[8][2];
#pragma unroll
        for (int i = 0; i < 8; i++) {
            acc[i][0] = pack2(bj.x, bj.y);
            acc[i][1] = pack2(bj.z, bj.w);
        }
#pragma unroll 4
        for (int d = 0; d < 128; d += 2) {
            ulonglong2 w0 = *(ulonglong2*)&W[d * 128 + jb];
            ulonglong2 w1 = *(ulonglong2*)&W[(d + 1) * 128 + jb];
#pragma unroll
            for (int i = 0; i < 8; i++) {
                float2 av = *(float2*)&os[(rb + i) * 128 + d];
                ull a0 = pack2(av.x, av.x), a1 = pack2(av.y, av.y);
                fma2(acc[i][0], a0, w0.x); fma2(acc[i][1], a0, w0.y);
                fma2(acc[i][0], a1, w1.x); fma2(acc[i][1], a1, w1.y);
            }
        }
        size_t row0 = (size_t)c * 64;
#pragma unroll
        for (int i = 0; i < 8; i++) {
            size_t r = row0 + rb + i;
            float4 s4 = *(const float4*)&g_self[r * 128 + jb];
            float2 u = unpack2(acc[i][0]), v = unpack2(acc[i][1]);
            float4 o = make_float4(fmaxf(u.x + s4.x, 0.f), fmaxf(u.y + s4.y, 0.f),
                                   fmaxf(v.x + s4.z, 0.f), fmaxf(v.y + s4.w, 0.f));
            *(float4*)&out[r * 128 + jb] = o;
        }
        __syncthreads();
        if (cn < 512) {
#pragma unroll
            for (int i = 0; i < 8; i++) *(float4*)&os[t * 32 + i * 4] = pfr[i];
        }
        __syncthreads();
        c = cn;
    }
}

// =====================================================================
// Launch
// =====================================================================
#define K1_SMEM 148480
#define KZ_SMEM ((128 * ZT_STR + 2 * KZ_QTILE) * 4)                    // 101376
#define K2_SMEM (K2_SMEMF * 4)                                         // 159744
#define K3A_SMEM ((128 * ZT_STR + 2 * MV_TILE + 128) * 4)              // 203264
#define K3_SMEM 98816

extern "C" void kernel_launch(void* const* d_in, const int* in_sizes, int n_in,
                              void* d_out, int out_size)
{
    const float* src   = (const float*)d_in[0];
    const float* nbr   = (const float*)d_in[1];
    const float* wq    = (const float*)d_in[2];
    const float* bq    = (const float*)d_in[3];
    const float* wkv   = (const float*)d_in[4];
    const float* bkv   = (const float*)d_in[5];
    const float* wo    = (const float*)d_in[6];
    const float* bo    = (const float*)d_in[7];
    const float* wself = (const float*)d_in[8];
    float* out = (float*)d_out;

    cudaFuncSetAttribute(k1_proj, cudaFuncAttributeMaxDynamicSharedMemorySize, K1_SMEM);
    cudaFuncSetAttribute(kz_proj, cudaFuncAttributeMaxDynamicSharedMemorySize, KZ_SMEM);
    cudaFuncSetAttribute(k2_attn, cudaFuncAttributeMaxDynamicSharedMemorySize, K2_SMEM);
    cudaFuncSetAttribute(k3a_v,   cudaFuncAttributeMaxDynamicSharedMemorySize, K3A_SMEM);
    cudaFuncSetAttribute(k3_out,  cudaFuncAttributeMaxDynamicSharedMemorySize, K3_SMEM);

    int dev = 0;
    cudaGetDevice(&dev);
    int nsm = 148;
    cudaDeviceGetAttribute(&nsm, cudaDevAttrMultiProcessorCount, dev);

    k1_proj<<<nsm, 256, K1_SMEM>>>(src, wq, bq, wself);
    kz_proj<<<2 * nsm, 256, KZ_SMEM>>>(wkv);
    k2_attn<<<nsm, 256, K2_SMEM>>>(nbr);
    k3a_v<<<nsm, 128, K3A_SMEM>>>(wkv, bkv);
    k3_out<<<nsm, 256, K3_SMEM>>>(wo, bo, out);
}

// round 13
// speedup vs baseline: 1.1380x; 1.0663x over previous
#include <cuda_runtime.h>
#include <cstdint>

// AttnSageGCN: B=32768 nodes, K=32 neighbors, D=128, HIDDEN=128 (4x32), H2=256
#define B_NODES 32768
#define SCALE_ATTN 0.17677669529663687f

typedef unsigned long long ull;

// Scratch (device globals; no runtime allocation allowed)
// g_m layout: per node 528 floats, element (h,j) at h*132 + j (conflict-free banks)
__device__ float g_self[(size_t)B_NODES * 128];
__device__ float g_z[(size_t)B_NODES * 512];    // per node, [h][d] (SCALE folded in)
__device__ float g_m[(size_t)B_NODES * 528];    // per node, [h*132 + j]
__device__ float g_v[(size_t)B_NODES * 128];    // attention output before wo

// ---------------- packed f32x2 helpers (FFMA2) ----------------
__device__ __forceinline__ ull pack2(float lo, float hi) {
    ull r; asm("mov.b64 %0, {%1, %2};" : "=l"(r) : "f"(lo), "f"(hi)); return r;
}
__device__ __forceinline__ float2 unpack2(ull v) {
    float2 f; asm("mov.b64 {%0, %1}, %2;" : "=f"(f.x), "=f"(f.y) : "l"(v)); return f;
}
__device__ __forceinline__ void fma2(ull& d, ull a, ull b) {
    asm("fma.rn.f32x2 %0, %1, %2, %0;" : "+l"(d) : "l"(a), "l"(b));
}

// ---------------- cp.async helpers (base-target, sm_80+) ----------------
__device__ __forceinline__ uint32_t smem_u32(const void* p) {
    uint32_t a;
    asm("{ .reg .u64 t; cvta.to.shared.u64 t, %1; cvt.u32.u64 %0, t; }" : "=r"(a) : "l"(p));
    return a;
}
__device__ __forceinline__ void cp16(uint32_t dst, const void* src) {
    asm volatile("cp.async.cg.shared.global [%0], [%1], 16;" :: "r"(dst), "l"(src) : "memory");
}
#define CP_COMMIT() asm volatile("cp.async.commit_group;" ::: "memory")
#define CP_WAIT0()  asm volatile("cp.async.wait_group 0;" ::: "memory")
#define CP_WAIT1()  asm volatile("cp.async.wait_group 1;" ::: "memory")

// =====================================================================
// Kernel 1Z (persistent, fused): q = src@wq + bq (SMEM only);
//   self = src@w_self -> g_self;  z[b][h][d] = SCALE * q_h . Wk[d]_h -> g_z
// SMEM: W(wq|wself) 32768 | bb 256 | WT(Wk^T) 128x132 | xq overlay 4224
// =====================================================================
#define ZT_STR 132
#define K1Z_XQ 49920
#define K1Z_SMEMF 54144     // 216576 bytes

__global__ void __launch_bounds__(256, 1) k1z(
    const float* __restrict__ src, const float* __restrict__ wq,
    const float* __restrict__ bq, const float* __restrict__ wself,
    const float* __restrict__ wkv)
{
    extern __shared__ float s1[];
    float* W  = s1;              // [128][256]
    float* bb = s1 + 32768;      // [256]
    float* WT = s1 + 33024;      // [128 cols][132]: WT[c][d] = wkv[d][c]
    float* xq = s1 + K1Z_XQ;     // overlay: xs[32][128] then qs[32][132]
    int t = threadIdx.x;

    for (int i = t; i < 16384; i += 256) {
        int d = i >> 7, j = i & 127;
        W[d * 256 + j]       = wq[i];
        W[d * 256 + 128 + j] = wself[i];
    }
    if (t < 128) { bb[t] = bq[t]; bb[128 + t] = 0.f; }
    {   // Wk transpose (cols 0..127 of wkv)
        int d = t >> 1, c0 = (t & 1) * 64;
#pragma unroll
        for (int i = 0; i < 16; i++) {
            float4 v = *(const float4*)&wkv[d * 256 + c0 + i * 4];
            WT[(c0 + i * 4 + 0) * ZT_STR + d] = v.x;
            WT[(c0 + i * 4 + 1) * ZT_STR + d] = v.y;
            WT[(c0 + i * 4 + 2) * ZT_STR + d] = v.z;
            WT[(c0 + i * 4 + 3) * ZT_STR + d] = v.w;
        }
    }
    int c = blockIdx.x;
    if (c < 1024) {
        size_t r0 = (size_t)c * 4096;
        for (int i = t * 4; i < 4096; i += 1024)
            *(float4*)&xq[i] = *(const float4*)&src[r0 + i];
    }
    __syncthreads();

    int tj = t & 63, tk = t >> 6;
    int jb = tj * 4, rb = tk * 8;
    int hd0 = (t & 63) * 8;
    int zh = hd0 >> 7, zd0 = hd0 & 127;
    int zg0 = (t >> 6) * 8;

    while (c < 1024) {
        int cn = c + gridDim.x;
        float4 pfr[4];
        if (cn < 1024) {
            const float4* s4 = (const float4*)&src[(size_t)cn * 4096 + t * 16];
#pragma unroll
            for (int i = 0; i < 4; i++) pfr[i] = s4[i];
        }
        // ---- q/self GEMM (xq as xs, stride 128) ----
        float4 bj = *(float4*)&bb[jb];
        ull acc[8][2];
#pragma unroll
        for (int i = 0; i < 8; i++) {
            acc[i][0] = pack2(bj.x, bj.y);
            acc[i][1] = pack2(bj.z, bj.w);
        }
#pragma unroll 4
        for (int d = 0; d < 128; d += 2) {
            ulonglong2 w0 = *(ulonglong2*)&W[d * 256 + jb];
            ulonglong2 w1 = *(ulonglong2*)&W[(d + 1) * 256 + jb];
#pragma unroll
            for (int i = 0; i < 8; i++) {
                float2 av = *(float2*)&xq[(rb + i) * 128 + d];
                ull a0 = pack2(av.x, av.x), a1 = pack2(av.y, av.y);
                fma2(acc[i][0], a0, w0.x); fma2(acc[i][1], a0, w0.y);
                fma2(acc[i][0], a1, w1.x); fma2(acc[i][1], a1, w1.y);
            }
        }
        __syncthreads();   // everyone done reading xs
        size_t row0 = (size_t)c * 32;
#pragma unroll
        for (int i = 0; i < 8; i++) {
            float2 u = unpack2(acc[i][0]), v = unpack2(acc[i][1]);
            float4 o = make_float4(u.x, u.y, v.x, v.y);
            if (jb < 128) *(float4*)&xq[(rb + i) * ZT_STR + jb] = o;         // q -> SMEM
            else *(float4*)&g_self[(row0 + rb + i) * 128 + (jb - 128)] = o;  // self -> HBM
        }
        __syncthreads();   // qs ready

        // ---- z phase (xq as qs, stride 132) ----
        ull zacc[8][4];
#pragma unroll
        for (int gg = 0; gg < 8; gg++)
#pragma unroll
            for (int i = 0; i < 4; i++) zacc[gg][i] = 0ULL;
#pragma unroll 4
        for (int j = 0; j < 32; j++) {
            const float* wr = &WT[(32 * zh + j) * ZT_STR + zd0];
            ulonglong2 w0 = *(const ulonglong2*)wr;
            ulonglong2 w1 = *(const ulonglong2*)(wr + 4);
#pragma unroll
            for (int gg = 0; gg < 8; gg++) {
                float qv = xq[(zg0 + gg) * ZT_STR + 32 * zh + j];
                ull qp = pack2(qv, qv);
                fma2(zacc[gg][0], qp, w0.x); fma2(zacc[gg][1], qp, w0.y);
                fma2(zacc[gg][2], qp, w1.x); fma2(zacc[gg][3], qp, w1.y);
            }
        }
#pragma unroll
        for (int gg = 0; gg < 8; gg++) {
            float2 a = unpack2(zacc[gg][0]), b = unpack2(zacc[gg][1]);
            float2 cc = unpack2(zacc[gg][2]), dd = unpack2(zacc[gg][3]);
            size_t base = (row0 + zg0 + gg) * 512 + hd0;
            *(float4*)&g_z[base] = make_float4(a.x * SCALE_ATTN, a.y * SCALE_ATTN,
                                               b.x * SCALE_ATTN, b.y * SCALE_ATTN);
            *(float4*)&g_z[base + 4] = make_float4(cc.x * SCALE_ATTN, cc.y * SCALE_ATTN,
                                                   dd.x * SCALE_ATTN, dd.y * SCALE_ATTN);
        }
        __syncthreads();   // everyone done reading qs
        if (cn < 1024) {
#pragma unroll
            for (int i = 0; i < 4; i++) *(float4*)&xq[t * 16 + i * 4] = pfr[i];
        }
        __syncthreads();
        c = cn;
    }
}

// =====================================================================
// Kernel 2: streaming attention, warp-per-node, 8 warps, RING-OF-3
// half-buffers per warp. Commit groups per node (FIFO):
//   G1 = z(next) after softmax; G2 = next second-half after m-part1;
//   G3 = next2 first-half after m-part2.  wait_group 1 at loop top.
// =====================================================================
#define NB_HALF 2112                     // 16 rows x 132
#define K2_OFF_ZB 50688                  // 8 warps x 3 x 2112
#define K2_OFF_PB 54784                  // + 8 x 512
#define K2_SMEMF 56832                   // 227328 bytes

__device__ __forceinline__ void k2_half(uint32_t dst_a, const float* __restrict__ src,
                                        int lane) {
#pragma unroll
    for (int i = 0; i < 16; i++)
        cp16(dst_a + i * 528 + lane * 16, src + i * 128 + lane * 4);
}

__global__ void __launch_bounds__(256, 1) k2_attn(const float* __restrict__ nbr)
{
    extern __shared__ float s2[];
    uint32_t sb = smem_u32(s2);
    int t = threadIdx.x, w = t >> 5, lane = t & 31;
    float* HB = s2 + w * 3 * NB_HALF;
    float* zb = s2 + K2_OFF_ZB + w * 512;
    float* pb = s2 + K2_OFF_PB + w * 256;
    uint32_t HBa = sb + (w * 3 * NB_HALF) * 4;
    uint32_t zba = sb + (K2_OFF_ZB + w * 512) * 4;

    int node = blockIdx.x * 8 + w;
    const int stride = gridDim.x * 8;
    int it3 = 0;

    if (node < B_NODES) {   // prologue: node0 full (slots 0,1) + z; node1 first (slot 2)
        const float* ns = nbr + (size_t)node * 4096;
        k2_half(HBa, ns, lane);
        k2_half(HBa + NB_HALF * 4, ns + 16 * 128, lane);
        const float* zsrc = g_z + (size_t)node * 512 + lane * 16;
#pragma unroll
        for (int i = 0; i < 4; i++) cp16(zba + lane * 64 + i * 16, zsrc + i * 4);
        CP_COMMIT();
        int n1 = node + stride;
        if (n1 < B_NODES) {
            k2_half(HBa + 2 * NB_HALF * 4, nbr + (size_t)n1 * 4096, lane);
            CP_COMMIT();
        }
    }

    while (node < B_NODES) {
        int nxt = node + stride;
        int nxt2 = node + 2 * stride;
        if (nxt < B_NODES) CP_WAIT1(); else CP_WAIT0();
        __syncwarp();
        // node slots: first = (2i)%3, second = (2i+1)%3 with i = iteration
        int sF = (it3 == 0) ? 0 : (it3 == 1 ? 2 : 1);
        int sS = (it3 == 0) ? 1 : (it3 == 1 ? 0 : 2);
        const float* nbF = HB + sF * NB_HALF;
        const float* nbS = HB + sS * NB_HALF;

        // ---- logits: lane = neighbor k (reads only its own row + zb) ----
        const float* row = (lane < 16) ? (nbF + lane * 132) : (nbS + (lane - 16) * 132);
        ull lga[4], lgb[4];
#pragma unroll
        for (int h = 0; h < 4; h++) { lga[h] = 0ULL; lgb[h] = 0ULL; }
#pragma unroll 4
        for (int d4 = 0; d4 < 32; d4++) {
            ulonglong2 nv = *(const ulonglong2*)(row + d4 * 4);
#pragma unroll
            for (int h = 0; h < 4; h++) {
                ulonglong2 zv = *(const ulonglong2*)(zb + h * 128 + d4 * 4);
                fma2(lga[h], nv.x, zv.x);
                fma2(lgb[h], nv.y, zv.y);
            }
        }
        float p[4];
#pragma unroll
        for (int h = 0; h < 4; h++) {
            float2 a = unpack2(lga[h]), b = unpack2(lgb[h]);
            float lg = (a.x + a.y) + (b.x + b.y);
            float mx = lg;
#pragma unroll
            for (int o = 16; o > 0; o >>= 1)
                mx = fmaxf(mx, __shfl_xor_sync(0xffffffffu, mx, o));
            float e = __expf(lg - mx);
            float sum = e;
#pragma unroll
            for (int o = 16; o > 0; o >>= 1)
                sum += __shfl_xor_sync(0xffffffffu, sum, o);
            p[h] = e / sum;
        }
        // store p DUPLICATED: pb[k*8 + 2h], pb[k*8 + 2h + 1] = p[h]
        *(float4*)&pb[lane * 8]     = make_float4(p[0], p[0], p[1], p[1]);
        *(float4*)&pb[lane * 8 + 4] = make_float4(p[2], p[2], p[3], p[3]);
        __syncwarp();                 // all lanes past logits (zb dead)

        if (nxt < B_NODES) {          // G1: z(next) into the single z buffer
            const float* zsrc = g_z + (size_t)nxt * 512 + lane * 16;
#pragma unroll
            for (int i = 0; i < 4; i++) cp16(zba + lane * 64 + i * 16, zsrc + i * 4);
            CP_COMMIT();
        }

        // ---- m (FFMA2): lane owns d-chunk [4*lane, 4*lane+4) ----
        ull mac[4][2];
#pragma unroll
        for (int h = 0; h < 4; h++) { mac[h][0] = 0ULL; mac[h][1] = 0ULL; }
#pragma unroll 4
        for (int k = 0; k < 16; k++) {     // part 1: rows in slot sF
            ulonglong2 pa = *(const ulonglong2*)&pb[k * 8];
            ulonglong2 pc = *(const ulonglong2*)&pb[k * 8 + 4];
            ulonglong2 nv = *(const ulonglong2*)&nbF[k * 132 + 4 * lane];
            fma2(mac[0][0], pa.x, nv.x); fma2(mac[0][1], pa.x, nv.y);
            fma2(mac[1][0], pa.y, nv.x); fma2(mac[1][1], pa.y, nv.y);
            fma2(mac[2][0], pc.x, nv.x); fma2(mac[2][1], pc.x, nv.y);
            fma2(mac[3][0], pc.y, nv.x); fma2(mac[3][1], pc.y, nv.y);
        }
        if (nxt < B_NODES) {          // G2: next SECOND half -> slot sF (just drained)
            __syncwarp();
            k2_half(HBa + sF * NB_HALF * 4, nbr + (size_t)nxt * 4096 + 16 * 128, lane);
            CP_COMMIT();
        }
#pragma unroll 4
        for (int k = 16; k < 32; k++) {    // part 2: rows in slot sS
            ulonglong2 pa = *(const ulonglong2*)&pb[k * 8];
            ulonglong2 pc = *(const ulonglong2*)&pb[k * 8 + 4];
            ulonglong2 nv = *(const ulonglong2*)&nbS[(k - 16) * 132 + 4 * lane];
            fma2(mac[0][0], pa.x, nv.x); fma2(mac[0][1], pa.x, nv.y);
            fma2(mac[1][0], pa.y, nv.x); fma2(mac[1][1], pa.y, nv.y);
            fma2(mac[2][0], pc.x, nv.x); fma2(mac[2][1], pc.x, nv.y);
            fma2(mac[3][0], pc.y, nv.x); fma2(mac[3][1], pc.y, nv.y);
        }
        if (nxt2 < B_NODES) {         // G3: next2 FIRST half -> slot sS (just drained)
            __syncwarp();
            k2_half(HBa + sS * NB_HALF * 4, nbr + (size_t)nxt2 * 4096, lane);
            CP_COMMIT();
        }

        size_t mb = (size_t)node * 528;
#pragma unroll
        for (int h = 0; h < 4; h++) {
            float2 u = unpack2(mac[h][0]), v = unpack2(mac[h][1]);
            *(float4*)&g_m[mb + h * 132 + 4 * lane] = make_float4(u.x, u.y, v.x, v.y);
        }

        node = nxt;
        it3 = (it3 == 2) ? 0 : it3 + 1;
    }
}

// =====================================================================
// Kernel 3a (persistent, double-buffered, LDS-minimized):
//   v[b][32h+c] = bv[32h+c] + sum_j m[b][h][j] * Wv[j][32h+c]
// =====================================================================
#define MV_STR 528
#define MV_TILE (32 * MV_STR)            // 16896 floats per m buffer
__global__ void __launch_bounds__(128, 1) k3a_v(
    const float* __restrict__ wkv, const float* __restrict__ bkv)
{
    extern __shared__ float sa[];
    float* Wv  = sa;                                  // [128][132]
    float* ms  = sa + 128 * ZT_STR;                   // 2 x [32 nodes][528]
    float* bvs = sa + 128 * ZT_STR + 2 * MV_TILE;     // [128]
    uint32_t ms_a = smem_u32(ms);
    int t = threadIdx.x;

    {   // Wv: row t of 128 floats
#pragma unroll 8
        for (int i = 0; i < 32; i++)
            *(float4*)&Wv[t * ZT_STR + i * 4] =
                *(const float4*)&wkv[t * 256 + 128 + i * 4];
    }
    if (t < 32) *(float4*)&bvs[t * 4] = *(const float4*)&bkv[128 + t * 4];

    int c = blockIdx.x;
    if (c < 1024) {   // linear copy: g_m tile stride matches SMEM stride (528)
        const float* src = g_m + (size_t)c * MV_TILE;
        for (int i = t; i < 4224; i += 128) cp16(ms_a + i * 16, src + i * 4);
        CP_COMMIT();
    }
    __syncthreads();   // Wv/bvs ready

    int c0 = (t & 31) * 4, h = c0 >> 5, g0 = (t >> 5) * 8;
    float4 bv4 = *(float4*)&bvs[c0];
    int buf = 0;

    while (c < 1024) {
        int cn = c + gridDim.x;
        if (cn < 1024) {
            const float* src = g_m + (size_t)cn * MV_TILE;
            uint32_t dst = ms_a + (buf ^ 1) * (MV_TILE * 4);
            for (int i = t; i < 4224; i += 128) cp16(dst + i * 16, src + i * 4);
            CP_COMMIT();
            CP_WAIT1();
        } else {
            CP_WAIT0();
        }
        __syncthreads();

        const float* msb = ms + buf * MV_TILE;
        size_t n0 = (size_t)c * 32;
        ull acc[8][2];
#pragma unroll
        for (int gg = 0; gg < 8; gg++) {
            acc[gg][0] = pack2(bv4.x, bv4.y);
            acc[gg][1] = pack2(bv4.z, bv4.w);
        }
#pragma unroll 4
        for (int j = 0; j < 128; j++) {
            ulonglong2 w2 = *(const ulonglong2*)&Wv[j * ZT_STR + c0];
#pragma unroll
            for (int gg = 0; gg < 8; gg++) {
                float mv = msb[(g0 + gg) * MV_STR + h * 132 + j];
                ull mp = pack2(mv, mv);
                fma2(acc[gg][0], mp, w2.x);
                fma2(acc[gg][1], mp, w2.y);
            }
        }
#pragma unroll
        for (int gg = 0; gg < 8; gg++) {
            float2 u = unpack2(acc[gg][0]), v = unpack2(acc[gg][1]);
            *(float4*)&g_v[(n0 + g0 + gg) * 128 + c0] = make_float4(u.x, u.y, v.x, v.y);
        }
        __syncthreads();   // all reads of buf done before refill
        buf ^= 1; c = cn;
    }
}

// =====================================================================
// Kernel 3b (persistent): out = relu(g_self + g_v @ wo + bo)
// =====================================================================
__global__ void __launch_bounds__(256, 1) k3_out(
    const float* __restrict__ wo, const float* __restrict__ bo,
    float* __restrict__ out)
{
    extern __shared__ float sm3[];
    float* W  = sm3;            // [128][128]
    float* bb = sm3 + 16384;    // [128]
    float* os = sm3 + 16512;    // [64][128]
    int t = threadIdx.x;

    for (int i = t * 4; i < 16384; i += 1024)
        *(float4*)&W[i] = *(const float4*)&wo[i];
    if (t < 32) *(float4*)&bb[t * 4] = *(const float4*)&bo[t * 4];
    int c = blockIdx.x;
    {
        size_t r0 = (size_t)c * 8192;
        for (int i = t * 4; i < 8192; i += 1024)
            *(float4*)&os[i] = *(const float4*)&g_v[r0 + i];
    }
    __syncthreads();

    int tj = t & 31, tk = t >> 5;
    int jb = tj * 4, rb = tk * 8;
    while (c < 512) {
        int cn = c + gridDim.x;
        float4 pfr[8];
        if (cn < 512) {
            const float4* s4 = (const float4*)&g_v[(size_t)cn * 8192 + t * 32];
#pragma unroll
            for (int i = 0; i < 8; i++) pfr[i] = s4[i];
        }
        float4 bj = *(float4*)&bb[jb];
        ull acc[8][2];
#pragma unroll
        for (int i = 0; i < 8; i++) {
            acc[i][0] = pack2(bj.x, bj.y);
            acc[i][1] = pack2(bj.z, bj.w);
        }
#pragma unroll 4
        for (int d = 0; d < 128; d += 2) {
            ulonglong2 w0 = *(ulonglong2*)&W[d * 128 + jb];
            ulonglong2 w1 = *(ulonglong2*)&W[(d + 1) * 128 + jb];
#pragma unroll
            for (int i = 0; i < 8; i++) {
                float2 av = *(float2*)&os[(rb + i) * 128 + d];
                ull a0 = pack2(av.x, av.x), a1 = pack2(av.y, av.y);
                fma2(acc[i][0], a0, w0.x); fma2(acc[i][1], a0, w0.y);
                fma2(acc[i][0], a1, w1.x); fma2(acc[i][1], a1, w1.y);
            }
        }
        size_t row0 = (size_t)c * 64;
#pragma unroll
        for (int i = 0; i < 8; i++) {
            size_t r = row0 + rb + i;
            float4 s4 = *(const float4*)&g_self[r * 128 + jb];
            float2 u = unpack2(acc[i][0]), v = unpack2(acc[i][1]);
            float4 o = make_float4(fmaxf(u.x + s4.x, 0.f), fmaxf(u.y + s4.y, 0.f),
                                   fmaxf(v.x + s4.z, 0.f), fmaxf(v.y + s4.w, 0.f));
            *(float4*)&out[r * 128 + jb] = o;
        }
        __syncthreads();
        if (cn < 512) {
#pragma unroll
            for (int i = 0; i < 8; i++) *(float4*)&os[t * 32 + i * 4] = pfr[i];
        }
        __syncthreads();
        c = cn;
    }
}

// =====================================================================
// Launch
// =====================================================================
#define K1Z_SMEM (K1Z_SMEMF * 4)                                       // 216576
#define K2_SMEM  (K2_SMEMF * 4)                                        // 227328
#define K3A_SMEM ((128 * ZT_STR + 2 * MV_TILE + 128) * 4)              // 203264
#define K3_SMEM  98816

extern "C" void kernel_launch(void* const* d_in, const int* in_sizes, int n_in,
                              void* d_out, int out_size)
{
    const float* src   = (const float*)d_in[0];
    const float* nbr   = (const float*)d_in[1];
    const float* wq    = (const float*)d_in[2];
    const float* bq    = (const float*)d_in[3];
    const float* wkv   = (const float*)d_in[4];
    const float* bkv   = (const float*)d_in[5];
    const float* wo    = (const float*)d_in[6];
    const float* bo    = (const float*)d_in[7];
    const float* wself = (const float*)d_in[8];
    float* out = (float*)d_out;

    cudaFuncSetAttribute(k1z,     cudaFuncAttributeMaxDynamicSharedMemorySize, K1Z_SMEM);
    cudaFuncSetAttribute(k2_attn, cudaFuncAttributeMaxDynamicSharedMemorySize, K2_SMEM);
    cudaFuncSetAttribute(k3a_v,   cudaFuncAttributeMaxDynamicSharedMemorySize, K3A_SMEM);
    cudaFuncSetAttribute(k3_out,  cudaFuncAttributeMaxDynamicSharedMemorySize, K3_SMEM);

    int dev = 0;
    cudaGetDevice(&dev);
    int nsm = 148;
    cudaDeviceGetAttribute(&nsm, cudaDevAttrMultiProcessorCount, dev);

    k1z<<<nsm, 256, K1Z_SMEM>>>(src, wq, bq, wself, wkv);
    k2_attn<<<nsm, 256, K2_SMEM>>>(nbr);
    k3a_v<<<nsm, 128, K3A_SMEM>>>(wkv, bkv);
    k3_out<<<nsm, 256, K3_SMEM>>>(wo, bo, out);
}